// round 10
// baseline (speedup 1.0000x reference)
#include <cuda_runtime.h>
#include <math.h>

// ---------------------------------------------------------------------------
// HMM forward (CgpHmmCell, nCodons=2): 24 states, CTX=6.
// 128-thread CTAs: 4 warps spread over all 4 SMSPs (32-thread CTAs pile every
// warp onto SMSP 0 via wid%4 — the round-2..6 bottleneck). 4 batch rows per
// warp, 8 lanes per row, 3 states per lane; 4 width-8 shfls per step; E loads
// double-buffered; packed ctx prefetched one 16-step block ahead.
// Deferred exact power-of-two renormalization every 16 steps.
// ---------------------------------------------------------------------------

#define NSTATES 24

__device__ float g_Wl[8][12];        // per-sublane edge weights (11 used)
__device__ float g_Bt4[216 * 32];    // emission float4: [ctx][sub][4] (k=3 pad)
__device__ float g_pi[32];           // softmax(init)

__constant__ int c_rcnt[24] = {2,1,1,4,1,1,3,1,1,2,1,1,1,2,1,1,2,1,1,2,1,1,2,1};
__constant__ int c_rcols[24][4] = {
  {0,1,0,0},{2,0,0,0},{3,0,0,0},{4,14,7,10},{5,0,0,0},{6,0,0,0},{7,17,10,0},
  {8,0,0,0},{9,0,0,0},{20,10,0,0},{11,0,0,0},{12,0,0,0},{13,0,0,0},{13,23,0,0},
  {15,0,0,0},{16,0,0,0},{4,14,0,0},{18,0,0,0},{19,0,0,0},{7,17,0,0},{21,0,0,0},
  {22,0,0,0},{10,20,0,0},{23,0,0,0}};

__constant__ int c_sr0[8] = {0,0,1,1,1,2,3,0};  // shfl of a0 (first)
__constant__ int c_sr1[8] = {0,0,0,2,0,0,0,0};  // shfl of a0 (second)
__constant__ int c_sr2[8] = {0,5,6,7,5,6,7,4};  // shfl of a1
__constant__ int c_sr3[8] = {0,0,1,2,3,4,5,6};  // shfl of a2

// ---------------------------------------------------------------------------
__global__ void setup_kernel(const float* __restrict__ w,
                             const float* __restrict__ ew,
                             const float* __restrict__ ik) {
  __shared__ float V[24][24];
  __shared__ float A[24][24];
  int tid = threadIdx.x;
  for (int i = tid; i < 576; i += blockDim.x) {
    ((float*)V)[i] = 0.f;
    ((float*)A)[i] = 0.f;
  }
  __syncthreads();
  if (tid == 0) {
    float w12 = w[12];
    V[0][0]  = 1.f - w[0]; V[0][1]  = w[0];
    V[1][2]  = 1.f;        V[2][3]  = 1.f;
    V[3][4]  = w[1];       V[6][7]  = w[2];
    V[4][5]  = 1.f; V[7][8] = 1.f; V[5][6] = 1.f; V[8][9] = 1.f;
    V[3][14] = w[3]; V[6][17] = w[4]; V[9][20] = w[5];
    V[9][10] = 1.f - w[5];
    V[14][15] = 1.f; V[17][18] = 1.f; V[20][21] = 1.f;
    V[15][16] = 1.f; V[18][19] = 1.f; V[21][22] = 1.f;
    V[16][4] = w[6]; V[19][7] = w[7]; V[22][10] = w[8];
    V[16][14] = 1.f - w[9]; V[19][17] = 1.f - w[10]; V[22][20] = 1.f - w[11];
    V[3][7]  = 1.f - w12 * w12;
    V[3][10] = 1.f - w12 * w12 * w12;
    V[6][10] = 1.f - w12 * w12;
    V[10][11] = 1.f; V[11][12] = 1.f; V[12][13] = 1.f;
    V[13][13] = 1.f; V[13][23] = 1.f; V[23][23] = 1.f;
  }
  __syncthreads();
  if (tid < 24) {
    int n = c_rcnt[tid];
    float m = -1e30f;
    for (int i = 0; i < n; ++i) m = fmaxf(m, V[tid][c_rcols[tid][i]]);
    float Z = 0.f;
    for (int i = 0; i < n; ++i) Z += expf(V[tid][c_rcols[tid][i]] - m);
    for (int i = 0; i < n; ++i) {
      int c = c_rcols[tid][i];
      A[tid][c] = expf(V[tid][c] - m) / Z;
    }
  }
  __syncthreads();
  // slots: 0:w0a(r0) 1:w0b(r3) | 2:wa(a0) 3:wb(a1) 4:wc(r0) 5:wd(r1) 6:we(r2)
  //        7:wf(a1) 8:wg(r0) 9:wh(r2) 10:wi(a2)
  if (tid == 0) {
    for (int s = 0; s < 8; ++s)
      for (int k = 0; k < 12; ++k) g_Wl[s][k] = 0.f;
    g_Wl[0][0]=A[0][0];  g_Wl[0][2]=A[0][1];   g_Wl[0][7]=A[1][2];
    g_Wl[1][1]=A[2][3];  g_Wl[1][2]=A[3][4];   g_Wl[1][6]=A[16][4];  g_Wl[1][7]=A[4][5];
    g_Wl[2][1]=A[5][6];  g_Wl[2][4]=A[3][7];   g_Wl[2][2]=A[6][7];   g_Wl[2][6]=A[19][7];  g_Wl[2][7]=A[7][8];
    g_Wl[3][1]=A[8][9];  g_Wl[3][4]=A[3][10];  g_Wl[3][5]=A[6][10];  g_Wl[3][2]=A[9][10];  g_Wl[3][6]=A[22][10]; g_Wl[3][7]=A[10][11];
    g_Wl[4][1]=A[11][12];g_Wl[4][2]=A[12][13]; g_Wl[4][3]=A[13][13]; g_Wl[4][8]=A[3][14];  g_Wl[4][9]=A[16][14];
    g_Wl[5][1]=A[14][15];g_Wl[5][2]=A[15][16]; g_Wl[5][8]=A[6][17];  g_Wl[5][9]=A[19][17];
    g_Wl[6][1]=A[17][18];g_Wl[6][2]=A[18][19]; g_Wl[6][8]=A[9][20];  g_Wl[6][9]=A[22][20];
    g_Wl[7][1]=A[20][21];g_Wl[7][2]=A[21][22]; g_Wl[7][9]=A[13][23]; g_Wl[7][10]=A[23][23];
  }
  if (tid == 32) {
    float m = -1e30f;
    for (int s = 0; s < NSTATES; ++s) m = fmaxf(m, ik[s]);
    float Z = 0.f;
    for (int s = 0; s < NSTATES; ++s) Z += expf(ik[s] - m);
    for (int s = 0; s < 32; ++s)
      g_pi[s] = (s < NSTATES) ? expf(ik[s] - m) / Z : 0.f;
  }
  for (int idx = tid; idx < 216 * 32; idx += blockDim.x) {
    int r = idx & 31, ctx = idx >> 5;
    int sub = r >> 2, k = r & 3;
    int pp = ctx / 36, rm = ctx - pp * 36;
    int p = rm / 6, c = rm - p * 6;
    float val = 0.f;
    if (k < 3) {
      int st = 3 * sub + k;
      val = 1.f / 6.f;
      if (st < 17 && pp < 4 && p < 4 && c < 4) {
        const float* e = ew + (((st * 4) + pp) * 4 + p) * 4;
        float m = fmaxf(fmaxf(e[0], e[1]), fmaxf(e[2], e[3]));
        float Z = expf(e[0] - m) + expf(e[1] - m) + expf(e[2] - m) + expf(e[3] - m);
        val = expf(e[c] - m) / Z;
      }
    }
    g_Bt4[idx] = val;
  }
}

// ---------------------------------------------------------------------------
// pack 16 ctx indices (8 bits each) into 4 uints; advances (pair, m1) carry
#define PACKW(dst, sx, sy, sz, sw)                                     \
  {                                                                    \
    int _c0 = pair * 6 + (sx); pair = m1 * 6 + (sx); m1 = (sx);        \
    int _c1 = pair * 6 + (sy); pair = m1 * 6 + (sy); m1 = (sy);        \
    int _c2 = pair * 6 + (sz); pair = m1 * 6 + (sz); m1 = (sz);        \
    int _c3 = pair * 6 + (sw); pair = m1 * 6 + (sw); m1 = (sw);        \
    dst = (unsigned)_c0 | ((unsigned)_c1 << 8) | ((unsigned)_c2 << 16) \
        | ((unsigned)_c3 << 24);                                       \
  }

// load 2 emission float4s from bytes [sh, sh+8) of packed word pk
#define LOAD2(d0, d1, pk, sh)                            \
  {                                                      \
    unsigned _w = (pk) >> (sh);                          \
    d0 = Bt[(int)(_w & 255u) * 8 + sub];                 \
    d1 = Bt[(int)((_w >> 8) & 255u) * 8 + sub];          \
  }

// one recurrence step: 4 width-8 shfls + small FMA tree, post-multiply by E
#define STEP(A0, A1, A2, Ev)                                                \
  {                                                                         \
    float _r0 = __shfl_sync(F, A0, sr0, 8);                                 \
    float _r1 = __shfl_sync(F, A0, sr1, 8);                                 \
    float _r2 = __shfl_sync(F, A1, sr2, 8);                                 \
    float _r3 = __shfl_sync(F, A2, sr3, 8);                                 \
    float _p1l = fmaf(wa, A0, wb * A1);                                     \
    float _p2l = fmaf(wf, A1, wi * A2);                                     \
    float _p0 = fmaf(w0a, _r0, w0b * _r3);                                  \
    float _p1 = _p1l + fmaf(wc, _r0, fmaf(wd, _r1, we * _r2));              \
    float _p2 = _p2l + fmaf(wg, _r0, wh * _r2);                             \
    A0 = _p0 * (Ev).x; A1 = _p1 * (Ev).y; A2 = _p2 * (Ev).z;                \
  }

__global__ void __launch_bounds__(128)
fwd_kernel(const int* __restrict__ seq, float* __restrict__ out, int T) {
  const unsigned F = 0xffffffffu;
  int lane = threadIdx.x & 31;
  int wid = threadIdx.x >> 5;          // 4 warps -> 4 different SMSPs
  int sub = lane & 7;
  int row = blockIdx.x * 16 + wid * 4 + (lane >> 3);
  const int4* sp = (const int4*)(seq + (long long)row * T);

  float w0a = g_Wl[sub][0], w0b = g_Wl[sub][1];
  float wa  = g_Wl[sub][2], wb  = g_Wl[sub][3], wc = g_Wl[sub][4];
  float wd  = g_Wl[sub][5], we  = g_Wl[sub][6];
  float wf  = g_Wl[sub][7], wg  = g_Wl[sub][8], wh = g_Wl[sub][9];
  float wi  = g_Wl[sub][10];
  int sr0 = c_sr0[sub], sr1 = c_sr1[sub], sr2 = c_sr2[sub], sr3 = c_sr3[sub];

  float a0 = g_pi[3 * sub + 0];
  float a1 = g_pi[3 * sub + 1];
  float a2 = g_pi[3 * sub + 2];

  const float4* Bt = (const float4*)g_Bt4;  // index: ctx*8 + sub

  int pair = 28, m1 = 4;       // start-context (prev2=4, prev1=4)
  float K = 0.f, pend = 1.f, zlast = 1.f;
  int eK = 0;
  int nblk = T >> 4;           // T = 2000 = 125*16

  // --- prologue: block 0 packed ctx; prefetch steps 0-1 --------------------
  unsigned cw0, cw1, cw2, cw3;
  {
    int4 t0 = sp[0], t1 = sp[1], t2 = sp[2], t3 = sp[3];
    PACKW(cw0, t0.x, t0.y, t0.z, t0.w);
    PACKW(cw1, t1.x, t1.y, t1.z, t1.w);
    PACKW(cw2, t2.x, t2.y, t2.z, t2.w);
    PACKW(cw3, t3.x, t3.y, t3.z, t3.w);
  }
  float4 X0, X1, Y0, Y1;       // double-buffered 2-step E chunks
  LOAD2(X0, X1, cw0, 0);

  for (int i = 0; i < nblk; ++i) {
    // prefetch next block's symbols -> packed ctx (last iter: dummy, unused)
    unsigned nw0, nw1, nw2, nw3;
    {
      int nb = (i + 1 < nblk) ? (i + 1) : 0;
      int4 t0 = sp[nb*4+0], t1 = sp[nb*4+1], t2 = sp[nb*4+2], t3 = sp[nb*4+3];
      PACKW(nw0, t0.x, t0.y, t0.z, t0.w);
      PACKW(nw1, t1.x, t1.y, t1.z, t1.w);
      PACKW(nw2, t2.x, t2.y, t2.z, t2.w);
      PACKW(nw3, t3.x, t3.y, t3.z, t3.w);
    }

    // steps 0-1; prefetch 2-3
    LOAD2(Y0, Y1, cw0, 16);
    if (i == 0) {                       // t=0: pred = pi (no transition)
      a0 *= X0.x; a1 *= X0.y; a2 *= X0.z;
    } else {
      STEP(a0, a1, a2, X0);
    }
    STEP(a0, a1, a2, X1);
    // steps 2-3; prefetch 4-5
    LOAD2(X0, X1, cw1, 0);
    STEP(a0, a1, a2, Y0); STEP(a0, a1, a2, Y1);
    // steps 4-5; prefetch 6-7
    LOAD2(Y0, Y1, cw1, 16);
    STEP(a0, a1, a2, X0); STEP(a0, a1, a2, X1);
    // steps 6-7; prefetch 8-9
    LOAD2(X0, X1, cw2, 0);
    STEP(a0, a1, a2, Y0); STEP(a0, a1, a2, Y1);
    // steps 8-9; prefetch 10-11
    LOAD2(Y0, Y1, cw2, 16);
    STEP(a0, a1, a2, X0); STEP(a0, a1, a2, X1);
    // steps 10-11; prefetch 12-13
    LOAD2(X0, X1, cw3, 0);
    STEP(a0, a1, a2, Y0); STEP(a0, a1, a2, Y1);
    // steps 12-13; prefetch 14-15
    LOAD2(Y0, Y1, cw3, 16);
    STEP(a0, a1, a2, X0); STEP(a0, a1, a2, X1);
    // steps 14-15; prefetch next block steps 0-1
    LOAD2(X0, X1, nw0, 0);
    STEP(a0, a1, a2, Y0); STEP(a0, a1, a2, Y1);

    // --- lagged exact power-of-two renorm (off critical path) --------------
    a0 *= pend; a1 *= pend; a2 *= pend;
    K += (float)eK;
    float z = a0 + a1 + a2;
    z += __shfl_xor_sync(F, z, 4, 8);
    z += __shfl_xor_sync(F, z, 2, 8);
    z += __shfl_xor_sync(F, z, 1, 8);
    int ez = ((__float_as_int(z) >> 23) & 0xff) - 127;
    pend = __int_as_float((127 - ez) << 23);  // 2^{-ez}, exact
    eK = ez;
    zlast = z;

    cw0 = nw0; cw1 = nw1; cw2 = nw2; cw3 = nw3;
  }

  if (sub == 0) out[row] = (__log2f(zlast) + K) * 0.69314718055994530942f;
}

// ---------------------------------------------------------------------------
extern "C" void kernel_launch(void* const* d_in, const int* in_sizes, int n_in,
                              void* d_out, int out_size) {
  const float* w  = (const float*)d_in[0];   // transition_kernel (240)
  const float* ew = (const float*)d_in[1];   // emission_kernel (1088)
  const float* ik = (const float*)d_in[2];   // init_kernel (24)
  const int* seq  = (const int*)d_in[3];     // (batch, T)
  float* out = (float*)d_out;

  int batch = out_size;                      // 2048
  int T = in_sizes[3] / batch;               // 2000

  setup_kernel<<<1, 256>>>(w, ew, ik);
  fwd_kernel<<<batch / 16, 128>>>(seq, out, T);
}

// round 11
// speedup vs baseline: 1.0743x; 1.0743x over previous
#include <cuda_runtime.h>
#include <math.h>

// ---------------------------------------------------------------------------
// HMM forward (CgpHmmCell, nCodons=2): 24 states, CTX=6.
// Lane = state (1 row per warp, 2048 warps).  TWO time-steps per shfl round:
// the 2-step composite transition graph also has max in-degree 4, so 4 shfls
// advance 2 steps.  Intermediate emissions are folded into a precomputed
// per-context table T1[216][32] (float4 of composite weights, 110KB, L1).
// Per round: 4 SHFL + 1 LDG.128 (T1) + 1 LDG (E2) + 5 FP.
// Deferred exact power-of-two renormalization every 16 steps (8 rounds).
// ---------------------------------------------------------------------------

__device__ float  g_A[24 * 24];      // dense softmaxed transition matrix
__device__ float  g_Bt[216 * 32];    // emission: Bt[ctx*32 + state] (pad 0)
__device__ float  g_pi[32];          // softmax(init), lanes>=24 -> 0
__device__ float4 g_W1[32];          // single-step weights A[src_k][s]
__device__ float4 g_T1[216 * 32];    // 2-step composite weights per (ctx1, s)

// row softmax structure of A
__constant__ int c_rcnt[24] = {2,1,1,4,1,1,3,1,1,2,1,1,1,2,1,1,2,1,1,2,1,1,2,1};
__constant__ int c_rcols[24][4] = {
  {0,1,0,0},{2,0,0,0},{3,0,0,0},{4,14,7,10},{5,0,0,0},{6,0,0,0},{7,17,10,0},
  {8,0,0,0},{9,0,0,0},{20,10,0,0},{11,0,0,0},{12,0,0,0},{13,0,0,0},{13,23,0,0},
  {15,0,0,0},{16,0,0,0},{4,14,0,0},{18,0,0,0},{19,0,0,0},{7,17,0,0},{21,0,0,0},
  {22,0,0,0},{10,20,0,0},{23,0,0,0}};

// 1-step in-lists (sources feeding state s), padded with 0
__constant__ int c_cnt1[32] = {1,1,1,1,2,1,1,3,1,1,4,1,1,2,2,1,1,2,1,1,2,1,1,2,
                               0,0,0,0,0,0,0,0};
__constant__ int c_in1[32][4] = {
  {0,0,0,0},{0,0,0,0},{1,0,0,0},{2,0,0,0},{3,16,0,0},{4,0,0,0},{5,0,0,0},
  {3,6,19,0},{7,0,0,0},{8,0,0,0},{3,6,9,22},{10,0,0,0},{11,0,0,0},{12,13,0,0},
  {3,16,0,0},{14,0,0,0},{15,0,0,0},{6,19,0,0},{17,0,0,0},{18,0,0,0},{9,22,0,0},
  {20,0,0,0},{21,0,0,0},{13,23,0,0},
  {0,0,0,0},{0,0,0,0},{0,0,0,0},{0,0,0,0},{0,0,0,0},{0,0,0,0},{0,0,0,0},{0,0,0,0}};

// 2-step in-lists in2(s) = union of in(m) for m in in(s), padded with 0
__constant__ int c_cnt2[32] = {1,1,1,1,2,2,1,3,3,1,4,4,1,3,2,2,1,2,2,1,2,2,1,3,
                               0,0,0,0,0,0,0,0};
__constant__ int c_in2[32][4] = {
  {0,0,0,0},{0,0,0,0},{0,0,0,0},{1,0,0,0},{2,15,0,0},{3,16,0,0},{4,0,0,0},
  {2,5,18,0},{3,6,19,0},{7,0,0,0},{2,5,8,21},{3,6,9,22},{10,0,0,0},
  {11,12,13,0},{2,15,0,0},{3,16,0,0},{14,0,0,0},{5,18,0,0},{6,19,0,0},
  {17,0,0,0},{8,21,0,0},{9,22,0,0},{20,0,0,0},{12,13,23,0},
  {0,0,0,0},{0,0,0,0},{0,0,0,0},{0,0,0,0},{0,0,0,0},{0,0,0,0},{0,0,0,0},{0,0,0,0}};

// ---------------------------------------------------------------------------
// setup1: build A (sparse row softmax), Bt[ctx][state], pi, W1
// ---------------------------------------------------------------------------
__global__ void setup1_kernel(const float* __restrict__ w,
                              const float* __restrict__ ew,
                              const float* __restrict__ ik) {
  __shared__ float V[24][24];
  __shared__ float A[24][24];
  int tid = threadIdx.x;
  for (int i = tid; i < 576; i += blockDim.x) {
    ((float*)V)[i] = 0.f;
    ((float*)A)[i] = 0.f;
  }
  __syncthreads();
  if (tid == 0) {
    float w12 = w[12];
    V[0][0]  = 1.f - w[0]; V[0][1]  = w[0];
    V[1][2]  = 1.f;        V[2][3]  = 1.f;
    V[3][4]  = w[1];       V[6][7]  = w[2];
    V[4][5]  = 1.f; V[7][8] = 1.f; V[5][6] = 1.f; V[8][9] = 1.f;
    V[3][14] = w[3]; V[6][17] = w[4]; V[9][20] = w[5];
    V[9][10] = 1.f - w[5];
    V[14][15] = 1.f; V[17][18] = 1.f; V[20][21] = 1.f;
    V[15][16] = 1.f; V[18][19] = 1.f; V[21][22] = 1.f;
    V[16][4] = w[6]; V[19][7] = w[7]; V[22][10] = w[8];
    V[16][14] = 1.f - w[9]; V[19][17] = 1.f - w[10]; V[22][20] = 1.f - w[11];
    V[3][7]  = 1.f - w12 * w12;
    V[3][10] = 1.f - w12 * w12 * w12;
    V[6][10] = 1.f - w12 * w12;
    V[10][11] = 1.f; V[11][12] = 1.f; V[12][13] = 1.f;
    V[13][13] = 1.f; V[13][23] = 1.f; V[23][23] = 1.f;
  }
  __syncthreads();
  if (tid < 24) {
    int n = c_rcnt[tid];
    float m = -1e30f;
    for (int i = 0; i < n; ++i) m = fmaxf(m, V[tid][c_rcols[tid][i]]);
    float Z = 0.f;
    for (int i = 0; i < n; ++i) Z += expf(V[tid][c_rcols[tid][i]] - m);
    for (int i = 0; i < n; ++i) {
      int c = c_rcols[tid][i];
      A[tid][c] = expf(V[tid][c] - m) / Z;
    }
  }
  __syncthreads();
  // publish A
  for (int i = tid; i < 576; i += blockDim.x) g_A[i] = ((float*)A)[i];
  // W1[s] = A[in1_k][s]
  if (tid < 32) {
    float4 wv = make_float4(0.f, 0.f, 0.f, 0.f);
    int n = c_cnt1[tid];
    if (n > 0) wv.x = A[c_in1[tid][0]][tid];
    if (n > 1) wv.y = A[c_in1[tid][1]][tid];
    if (n > 2) wv.z = A[c_in1[tid][2]][tid];
    if (n > 3) wv.w = A[c_in1[tid][3]][tid];
    g_W1[tid] = wv;
  }
  if (tid == 32) {
    float m = -1e30f;
    for (int s = 0; s < 24; ++s) m = fmaxf(m, ik[s]);
    float Z = 0.f;
    for (int s = 0; s < 24; ++s) Z += expf(ik[s] - m);
    for (int s = 0; s < 32; ++s)
      g_pi[s] = (s < 24) ? expf(ik[s] - m) / Z : 0.f;
  }
  // emission table Bt[ctx*32 + s]; ctx = (pp*6+p)*6+c
  for (int idx = tid; idx < 216 * 32; idx += blockDim.x) {
    int s = idx & 31, ctx = idx >> 5;
    int pp = ctx / 36, rm = ctx - pp * 36;
    int p = rm / 6, c = rm - p * 6;
    float val = 0.f;
    if (s < 24) {
      val = 1.f / 6.f;
      if (s < 17 && pp < 4 && p < 4 && c < 4) {
        const float* e = ew + (((s * 4) + pp) * 4 + p) * 4;
        float m = fmaxf(fmaxf(e[0], e[1]), fmaxf(e[2], e[3]));
        float Z = expf(e[0] - m) + expf(e[1] - m) + expf(e[2] - m) + expf(e[3] - m);
        val = expf(e[c] - m) / Z;
      }
    }
    g_Bt[idx] = val;
  }
}

// ---------------------------------------------------------------------------
// setup2: T1[ctx][s].k = sum over 2-paths (q=in2_k -> m -> s) of
//         A[q][m] * E_ctx[m] * A[m][s]   (handles multi-path 13->23 case)
// ---------------------------------------------------------------------------
__global__ void setup2_kernel() {
  int ctx = blockIdx.x;      // 216 blocks
  int s = threadIdx.x;       // 32 threads
  float co[4] = {0.f, 0.f, 0.f, 0.f};
  if (s < 24) {
    int n1 = c_cnt1[s];
    for (int a = 0; a < n1; ++a) {
      int m = c_in1[s][a];
      float wms = g_A[m * 24 + s] * g_Bt[ctx * 32 + m];
      int nm = c_cnt1[m];
      for (int b = 0; b < nm; ++b) {
        int q = c_in1[m][b];
        float wqm = g_A[q * 24 + m];
        int n2 = c_cnt2[s];
        for (int k = 0; k < n2; ++k)
          if (c_in2[s][k] == q) { co[k] += wqm * wms; break; }
      }
    }
  }
  g_T1[ctx * 32 + s] = make_float4(co[0], co[1], co[2], co[3]);
}

// ---------------------------------------------------------------------------
// pack 16 ctx indices (8 bits each) into 4 uints; advances (pair, m1) carry
#define PACKW(dst, sx, sy, sz, sw)                                     \
  {                                                                    \
    int _c0 = pair * 6 + (sx); pair = m1 * 6 + (sx); m1 = (sx);        \
    int _c1 = pair * 6 + (sy); pair = m1 * 6 + (sy); m1 = (sy);        \
    int _c2 = pair * 6 + (sz); pair = m1 * 6 + (sz); m1 = (sz);        \
    int _c3 = pair * 6 + (sw); pair = m1 * 6 + (sw); m1 = (sw);        \
    dst = (unsigned)_c0 | ((unsigned)_c1 << 8) | ((unsigned)_c2 << 16) \
        | ((unsigned)_c3 << 24);                                       \
  }

// one 2-step round: ctx1/ctx2 are bytes sh, sh+8 of packed word pk
#define ROUND(pk, sh)                                                   \
  {                                                                     \
    unsigned _w = (pk) >> (sh);                                         \
    int _c1 = (int)(_w & 255u);                                         \
    int _c2 = (int)((_w >> 8) & 255u);                                  \
    float4 _t = T1p[_c1 * 32 + lane];                                   \
    float _e2 = Btp[_c2 * 32 + lane];                                   \
    float _r0 = __shfl_sync(F, alpha, s20);                             \
    float _r1 = __shfl_sync(F, alpha, s21);                             \
    float _r2 = __shfl_sync(F, alpha, s22);                             \
    float _r3 = __shfl_sync(F, alpha, s23);                             \
    float _acc = fmaf(_t.y, _r1, _t.x * _r0);                           \
    _acc = fmaf(_t.z, _r2, _acc);                                       \
    _acc = fmaf(_t.w, _r3, _acc);                                       \
    alpha = _acc * _e2;                                                 \
  }

// lagged exact power-of-two renorm (full-warp butterfly; idle lanes hold 0)
#define RENORM()                                                \
  {                                                             \
    alpha *= pend;                                              \
    K += (float)eK;                                             \
    float _z = alpha;                                           \
    _z += __shfl_xor_sync(F, _z, 16);                           \
    _z += __shfl_xor_sync(F, _z, 8);                            \
    _z += __shfl_xor_sync(F, _z, 4);                            \
    _z += __shfl_xor_sync(F, _z, 2);                            \
    _z += __shfl_xor_sync(F, _z, 1);                            \
    int _ez = ((__float_as_int(_z) >> 23) & 0xff) - 127;        \
    pend = __int_as_float((127 - _ez) << 23);                   \
    eK = _ez;                                                   \
    zlast = _z;                                                 \
  }

__global__ void __launch_bounds__(128)
fwd_kernel(const int* __restrict__ seq, float* __restrict__ out, int T) {
  const unsigned F = 0xffffffffu;
  int lane = threadIdx.x & 31;
  int wid = threadIdx.x >> 5;
  int row = blockIdx.x * 4 + wid;     // one row per warp
  const int4* sp = (const int4*)(seq + (long long)row * T);

  const float4* T1p = g_T1;
  const float*  Btp = g_Bt;

  int s20 = c_in2[lane][0], s21 = c_in2[lane][1];
  int s22 = c_in2[lane][2], s23 = c_in2[lane][3];
  float4 W1 = g_W1[lane];
  int s10 = c_in1[lane][0], s11 = c_in1[lane][1];
  int s12 = c_in1[lane][2], s13 = c_in1[lane][3];

  float alpha = g_pi[lane];           // 0 for lanes >= 24

  int pair = 28, m1 = 4;              // start-context (prev2=4, prev1=4)
  float K = 0.f, pend = 1.f, zlast = 1.f;
  int eK = 0;
  int nblk = T >> 4;                  // 125 blocks of 16 steps

  // --- block 0 symbols -> packed ctx ---------------------------------------
  unsigned cw0, cw1, cw2, cw3;
  {
    int4 t0 = sp[0], t1 = sp[1], t2 = sp[2], t3 = sp[3];
    PACKW(cw0, t0.x, t0.y, t0.z, t0.w);
    PACKW(cw1, t1.x, t1.y, t1.z, t1.w);
    PACKW(cw2, t2.x, t2.y, t2.z, t2.w);
    PACKW(cw3, t3.x, t3.y, t3.z, t3.w);
  }

  // --- t = 0: alpha = pi * E(ctx0) -----------------------------------------
  {
    int c0 = (int)(cw0 & 255u);
    alpha *= Btp[c0 * 32 + lane];
  }
  // --- t = 1: single step (same shfl structure, weights W1) ----------------
  {
    int c1 = (int)((cw0 >> 8) & 255u);
    float e1 = Btp[c1 * 32 + lane];
    float r0 = __shfl_sync(F, alpha, s10);
    float r1 = __shfl_sync(F, alpha, s11);
    float r2 = __shfl_sync(F, alpha, s12);
    float r3 = __shfl_sync(F, alpha, s13);
    float acc = fmaf(W1.y, r1, W1.x * r0);
    acc = fmaf(W1.z, r2, acc);
    acc = fmaf(W1.w, r3, acc);
    alpha = acc * e1;
  }
  // --- 7 rounds covering steps 2..15 of block 0 ----------------------------
  {
    // prefetch block 1 symbols
    int4 t0 = sp[4], t1 = sp[5], t2 = sp[6], t3 = sp[7];
    unsigned nw0, nw1, nw2, nw3;
    PACKW(nw0, t0.x, t0.y, t0.z, t0.w);
    PACKW(nw1, t1.x, t1.y, t1.z, t1.w);
    PACKW(nw2, t2.x, t2.y, t2.z, t2.w);
    PACKW(nw3, t3.x, t3.y, t3.z, t3.w);

    ROUND(cw0, 16);
    ROUND(cw1, 0);  ROUND(cw1, 16);
    ROUND(cw2, 0);  ROUND(cw2, 16);
    ROUND(cw3, 0);  ROUND(cw3, 16);
    RENORM();

    cw0 = nw0; cw1 = nw1; cw2 = nw2; cw3 = nw3;
  }

  // --- main: blocks 1..124, 8 rounds each ----------------------------------
  for (int i = 1; i < nblk; ++i) {
    unsigned nw0, nw1, nw2, nw3;
    {
      int nb = (i + 1 < nblk) ? (i + 1) : 0;   // last iter: dummy, unused
      int4 t0 = sp[nb*4+0], t1 = sp[nb*4+1], t2 = sp[nb*4+2], t3 = sp[nb*4+3];
      PACKW(nw0, t0.x, t0.y, t0.z, t0.w);
      PACKW(nw1, t1.x, t1.y, t1.z, t1.w);
      PACKW(nw2, t2.x, t2.y, t2.z, t2.w);
      PACKW(nw3, t3.x, t3.y, t3.z, t3.w);
    }

    ROUND(cw0, 0);  ROUND(cw0, 16);
    ROUND(cw1, 0);  ROUND(cw1, 16);
    ROUND(cw2, 0);  ROUND(cw2, 16);
    ROUND(cw3, 0);  ROUND(cw3, 16);
    RENORM();

    cw0 = nw0; cw1 = nw1; cw2 = nw2; cw3 = nw3;
  }

  if (lane == 0) out[row] = (__log2f(zlast) + K) * 0.69314718055994530942f;
}

// ---------------------------------------------------------------------------
extern "C" void kernel_launch(void* const* d_in, const int* in_sizes, int n_in,
                              void* d_out, int out_size) {
  const float* w  = (const float*)d_in[0];   // transition_kernel (240)
  const float* ew = (const float*)d_in[1];   // emission_kernel (1088)
  const float* ik = (const float*)d_in[2];   // init_kernel (24)
  const int* seq  = (const int*)d_in[3];     // (batch, T)
  float* out = (float*)d_out;

  int batch = out_size;                      // 2048
  int T = in_sizes[3] / batch;               // 2000

  setup1_kernel<<<1, 256>>>(w, ew, ik);
  setup2_kernel<<<216, 32>>>();
  fwd_kernel<<<batch / 4, 128>>>(seq, out, T);
}

// round 12
// speedup vs baseline: 1.0953x; 1.0195x over previous
#include <cuda_runtime.h>
#include <math.h>

// ---------------------------------------------------------------------------
// HMM forward (CgpHmmCell, nCodons=2): 24 states, CTX=6.
// Lane = state, one row per warp (2048 warps).  THREE time-steps per shfl
// round: the 3-step composite transition graph also has max in-degree 4, so 4
// shfls advance 3 steps.  Both intermediate emissions fold into a precomputed
// table T2[(ctx1, sym2)][s] (1296 x 32 x float4 = 663KB, L2-resident; rounds
// prefetched 2 ahead through 4 rotating buffers).  Per round: 4 SHFL +
// 1 LDG.128 + 1 LDG + 4 FP.  Renorm (exact power-of-two) every 8 rounds.
// ---------------------------------------------------------------------------

__device__ float  g_A[24 * 24];      // dense softmaxed transition matrix
__device__ float  g_Bt[216 * 32];    // emission: Bt[ctx*32 + state] (pad 0)
__device__ float  g_pi[32];          // softmax(init), lanes>=24 -> 0
__device__ float4 g_W1[32];          // single-step weights A[src_k][s]
__device__ float4 g_T2[1296 * 32];   // 3-step composite weights

// row softmax structure of A
__constant__ int c_rcnt[24] = {2,1,1,4,1,1,3,1,1,2,1,1,1,2,1,1,2,1,1,2,1,1,2,1};
__constant__ int c_rcols[24][4] = {
  {0,1,0,0},{2,0,0,0},{3,0,0,0},{4,14,7,10},{5,0,0,0},{6,0,0,0},{7,17,10,0},
  {8,0,0,0},{9,0,0,0},{20,10,0,0},{11,0,0,0},{12,0,0,0},{13,0,0,0},{13,23,0,0},
  {15,0,0,0},{16,0,0,0},{4,14,0,0},{18,0,0,0},{19,0,0,0},{7,17,0,0},{21,0,0,0},
  {22,0,0,0},{10,20,0,0},{23,0,0,0}};

// 1-step in-lists (sources feeding state s), padded with 0
__constant__ int c_cnt1[32] = {1,1,1,1,2,1,1,3,1,1,4,1,1,2,2,1,1,2,1,1,2,1,1,2,
                               0,0,0,0,0,0,0,0};
__constant__ int c_in1[32][4] = {
  {0,0,0,0},{0,0,0,0},{1,0,0,0},{2,0,0,0},{3,16,0,0},{4,0,0,0},{5,0,0,0},
  {3,6,19,0},{7,0,0,0},{8,0,0,0},{3,6,9,22},{10,0,0,0},{11,0,0,0},{12,13,0,0},
  {3,16,0,0},{14,0,0,0},{15,0,0,0},{6,19,0,0},{17,0,0,0},{18,0,0,0},{9,22,0,0},
  {20,0,0,0},{21,0,0,0},{13,23,0,0},
  {0,0,0,0},{0,0,0,0},{0,0,0,0},{0,0,0,0},{0,0,0,0},{0,0,0,0},{0,0,0,0},{0,0,0,0}};

// 3-step in-lists in3(s), padded with 0
__constant__ int c_cnt3[32] = {1,1,1,1,2,2,2,3,3,3,4,4,4,4,2,2,2,2,2,2,2,2,2,4,
                               0,0,0,0,0,0,0,0};
__constant__ int c_in3[32][4] = {
  {0,0,0,0},{0,0,0,0},{0,0,0,0},{0,0,0,0},{1,14,0,0},{2,15,0,0},{3,16,0,0},
  {1,4,17,0},{2,5,18,0},{3,6,19,0},{1,4,7,20},{2,5,8,21},{3,6,9,22},
  {10,11,12,13},{1,14,0,0},{2,15,0,0},{3,16,0,0},{4,17,0,0},{5,18,0,0},
  {6,19,0,0},{7,20,0,0},{8,21,0,0},{9,22,0,0},{11,12,13,23},
  {0,0,0,0},{0,0,0,0},{0,0,0,0},{0,0,0,0},{0,0,0,0},{0,0,0,0},{0,0,0,0},{0,0,0,0}};

// ---------------------------------------------------------------------------
// setup1: A (sparse row softmax), Bt, pi, W1.  Fast __expf (tolerance 1e-3).
// ---------------------------------------------------------------------------
__global__ void setup1_kernel(const float* __restrict__ w,
                              const float* __restrict__ ew,
                              const float* __restrict__ ik) {
  __shared__ float V[24][24];
  __shared__ float A[24][24];
  int tid = threadIdx.x;
  for (int i = tid; i < 576; i += blockDim.x) {
    ((float*)V)[i] = 0.f;
    ((float*)A)[i] = 0.f;
  }
  __syncthreads();
  if (tid == 0) {
    float w12 = w[12];
    V[0][0]  = 1.f - w[0]; V[0][1]  = w[0];
    V[1][2]  = 1.f;        V[2][3]  = 1.f;
    V[3][4]  = w[1];       V[6][7]  = w[2];
    V[4][5]  = 1.f; V[7][8] = 1.f; V[5][6] = 1.f; V[8][9] = 1.f;
    V[3][14] = w[3]; V[6][17] = w[4]; V[9][20] = w[5];
    V[9][10] = 1.f - w[5];
    V[14][15] = 1.f; V[17][18] = 1.f; V[20][21] = 1.f;
    V[15][16] = 1.f; V[18][19] = 1.f; V[21][22] = 1.f;
    V[16][4] = w[6]; V[19][7] = w[7]; V[22][10] = w[8];
    V[16][14] = 1.f - w[9]; V[19][17] = 1.f - w[10]; V[22][20] = 1.f - w[11];
    V[3][7]  = 1.f - w12 * w12;
    V[3][10] = 1.f - w12 * w12 * w12;
    V[6][10] = 1.f - w12 * w12;
    V[10][11] = 1.f; V[11][12] = 1.f; V[12][13] = 1.f;
    V[13][13] = 1.f; V[13][23] = 1.f; V[23][23] = 1.f;
  }
  __syncthreads();
  if (tid < 24) {
    int n = c_rcnt[tid];
    float m = -1e30f;
    for (int i = 0; i < n; ++i) m = fmaxf(m, V[tid][c_rcols[tid][i]]);
    float Z = 0.f;
    for (int i = 0; i < n; ++i) Z += __expf(V[tid][c_rcols[tid][i]] - m);
    for (int i = 0; i < n; ++i) {
      int c = c_rcols[tid][i];
      A[tid][c] = __expf(V[tid][c] - m) / Z;
    }
  }
  __syncthreads();
  for (int i = tid; i < 576; i += blockDim.x) g_A[i] = ((float*)A)[i];
  if (tid < 32) {
    float4 wv = make_float4(0.f, 0.f, 0.f, 0.f);
    int n = c_cnt1[tid];
    if (n > 0) wv.x = A[c_in1[tid][0]][tid];
    if (n > 1) wv.y = A[c_in1[tid][1]][tid];
    if (n > 2) wv.z = A[c_in1[tid][2]][tid];
    if (n > 3) wv.w = A[c_in1[tid][3]][tid];
    g_W1[tid] = wv;
  }
  if (tid == 32) {
    float m = -1e30f;
    for (int s = 0; s < 24; ++s) m = fmaxf(m, ik[s]);
    float Z = 0.f;
    for (int s = 0; s < 24; ++s) Z += __expf(ik[s] - m);
    for (int s = 0; s < 32; ++s)
      g_pi[s] = (s < 24) ? __expf(ik[s] - m) / Z : 0.f;
  }
  for (int idx = tid; idx < 216 * 32; idx += blockDim.x) {
    int s = idx & 31, ctx = idx >> 5;
    int pp = ctx / 36, rm = ctx - pp * 36;
    int p = rm / 6, c = rm - p * 6;
    float val = 0.f;
    if (s < 24) {
      val = 1.f / 6.f;
      if (s < 17 && pp < 4 && p < 4 && c < 4) {
        const float* e = ew + (((s * 4) + pp) * 4 + p) * 4;
        float m = fmaxf(fmaxf(e[0], e[1]), fmaxf(e[2], e[3]));
        float Z = __expf(e[0] - m) + __expf(e[1] - m) +
                  __expf(e[2] - m) + __expf(e[3] - m);
        val = __expf(e[c] - m) / Z;
      }
    }
    g_Bt[idx] = val;
  }
}

// ---------------------------------------------------------------------------
// setup2: T2[(c1*6+s2)][s].k = sum over 3-paths q=in3_k -> m1 -> m2 -> s of
//   A[q][m1]*E[c1][m1]*A[m1][m2]*E[c2][m2]*A[m2][s],  c2=(c1%36)*6+s2
// ---------------------------------------------------------------------------
__global__ void setup2_kernel() {
  int bid = blockIdx.x;      // 1296
  int c1 = bid / 6, s2 = bid - c1 * 6;
  int c2 = (c1 % 36) * 6 + s2;
  int s = threadIdx.x;       // 32
  float co[4] = {0.f, 0.f, 0.f, 0.f};
  if (s < 24) {
    int n2 = c_cnt1[s];
    for (int a = 0; a < n2; ++a) {
      int m2 = c_in1[s][a];
      float w2 = g_A[m2 * 24 + s] * g_Bt[c2 * 32 + m2];
      int nm = c_cnt1[m2];
      for (int b = 0; b < nm; ++b) {
        int m1 = c_in1[m2][b];
        float w1v = g_A[m1 * 24 + m2] * g_Bt[c1 * 32 + m1] * w2;
        int nq = c_cnt1[m1];
        for (int d = 0; d < nq; ++d) {
          int q = c_in1[m1][d];
          float wq = g_A[q * 24 + m1] * w1v;
          int n3 = c_cnt3[s];
          for (int k = 0; k < n3; ++k)
            if (c_in3[s][k] == q) { co[k] += wq; break; }
        }
      }
    }
  }
  g_T2[bid * 32 + s] = make_float4(co[0], co[1], co[2], co[3]);
}

// ---------------------------------------------------------------------------
// make a 3-step round descriptor from symbols (s1,s2,s3); carries 'pair'
//   rd = (c1*6+s2) | (c3 << 12)
#define MKRD(dst, s1, s2, s3)                                   \
  {                                                             \
    int _c1 = pair * 6 + (s1);                                  \
    int _i  = _c1 * 6 + (s2);                                   \
    int _c3 = ((s1) * 6 + (s2)) * 6 + (s3);                     \
    pair = (s2) * 6 + (s3);                                     \
    dst = (unsigned)_i | ((unsigned)_c3 << 12);                 \
  }

// prefetch round tables from descriptor
#define PF(Tv, Ev, rd)                                          \
  {                                                             \
    int _i = (int)((rd) & 4095u);                               \
    int _c = (int)((rd) >> 12);                                 \
    Tv = T2p[_i * 32 + lane];                                   \
    Ev = Btp[_c * 32 + lane];                                   \
  }

// one 3-step round
#define ROUND(Tv, Ev)                                           \
  {                                                             \
    float _r0 = __shfl_sync(F, alpha, s30);                     \
    float _r1 = __shfl_sync(F, alpha, s31);                     \
    float _r2 = __shfl_sync(F, alpha, s32);                     \
    float _r3 = __shfl_sync(F, alpha, s33);                     \
    float _acc = fmaf((Tv).y, _r1, (Tv).x * _r0);               \
    _acc = fmaf((Tv).z, _r2, _acc);                             \
    _acc = fmaf((Tv).w, _r3, _acc);                             \
    alpha = _acc * (Ev);                                        \
  }

// lagged exact power-of-two renorm (full-warp butterfly; idle lanes hold 0)
#define RENORM()                                                \
  {                                                             \
    alpha *= pend;                                              \
    K += (float)eK;                                             \
    float _z = alpha;                                           \
    _z += __shfl_xor_sync(F, _z, 16);                           \
    _z += __shfl_xor_sync(F, _z, 8);                            \
    _z += __shfl_xor_sync(F, _z, 4);                            \
    _z += __shfl_xor_sync(F, _z, 2);                            \
    _z += __shfl_xor_sync(F, _z, 1);                            \
    int _ez = ((__float_as_int(_z) >> 23) & 0xff) - 127;        \
    pend = __int_as_float((127 - _ez) << 23);                   \
    eK = _ez;                                                   \
    zlast = _z;                                                 \
  }

// pack one block (24 syms: carry cc0,cc1 + chunks t1..t6) into 8 descriptors
#define PACK8(D0,D1,D2,D3,D4,D5,D6,D7, base)                    \
  {                                                             \
    int4 t1 = sp[(base)+1], t2 = sp[(base)+2], t3 = sp[(base)+3]; \
    int4 t4 = sp[(base)+4], t5 = sp[(base)+5], t6 = sp[(base)+6]; \
    MKRD(D0, cc0, cc1, t1.x);                                   \
    MKRD(D1, t1.y, t1.z, t1.w);                                 \
    MKRD(D2, t2.x, t2.y, t2.z);                                 \
    MKRD(D3, t2.w, t3.x, t3.y);                                 \
    MKRD(D4, t3.z, t3.w, t4.x);                                 \
    MKRD(D5, t4.y, t4.z, t4.w);                                 \
    MKRD(D6, t5.x, t5.y, t5.z);                                 \
    MKRD(D7, t5.w, t6.x, t6.y);                                 \
    cc0 = t6.z; cc1 = t6.w;                                     \
  }

__global__ void __launch_bounds__(128)
fwd_kernel(const int* __restrict__ seq, float* __restrict__ out, int T) {
  const unsigned F = 0xffffffffu;
  int lane = threadIdx.x & 31;
  int wid = threadIdx.x >> 5;
  int row = blockIdx.x * 4 + wid;     // one row per warp
  const int4* sp = (const int4*)(seq + (long long)row * T);

  const float4* T2p = g_T2;
  const float*  Btp = g_Bt;

  int s30 = c_in3[lane][0], s31 = c_in3[lane][1];
  int s32 = c_in3[lane][2], s33 = c_in3[lane][3];
  float4 W1 = g_W1[lane];
  int s10 = c_in1[lane][0], s11 = c_in1[lane][1];
  int s12 = c_in1[lane][2], s13 = c_in1[lane][3];

  float alpha = g_pi[lane];           // 0 for lanes >= 24

  int pair = 28;                      // start-context (prev2=4, prev1=4)
  float K = 0.f, pend = 1.f, zlast = 1.f;
  int eK = 0;

  // layout for T = 2000: steps 0,1 explicit; 83 blocks x 8 rounds (24 steps);
  // tail 2 rounds (6 steps).  2 + 1992 + 6 = 2000.
  int cc0, cc1;
  // --- prologue: steps 0 and 1 ---------------------------------------------
  {
    int4 t0 = sp[0];
    int c0 = pair * 6 + t0.x;         // ctx (4,4,s0)
    alpha *= Btp[c0 * 32 + lane];
    pair = 4 * 6 + t0.x;              // (4, s0)
    int c1 = pair * 6 + t0.y;
    float e1 = Btp[c1 * 32 + lane];
    float r0 = __shfl_sync(F, alpha, s10);
    float r1 = __shfl_sync(F, alpha, s11);
    float r2 = __shfl_sync(F, alpha, s12);
    float r3 = __shfl_sync(F, alpha, s13);
    float acc = fmaf(W1.y, r1, W1.x * r0);
    acc = fmaf(W1.z, r2, acc);
    acc = fmaf(W1.w, r3, acc);
    alpha = acc * e1;
    pair = t0.x * 6 + t0.y;
    cc0 = t0.z; cc1 = t0.w;           // carry syms 2,3
  }

  unsigned rd0, rd1, rd2, rd3, rd4, rd5, rd6, rd7;
  unsigned nd0, nd1, nd2, nd3, nd4, nd5, nd6, nd7;
  PACK8(rd0, rd1, rd2, rd3, rd4, rd5, rd6, rd7, 0);   // block 0 (chunks 1..6)

  float4 T0v, T1v, T2v, T3v;
  float  E0v, E1v, E2v, E3v;
  PF(T0v, E0v, rd0);
  PF(T1v, E1v, rd1);

  for (int b = 0; b < 83; ++b) {
    if (b < 82) {
      PACK8(nd0, nd1, nd2, nd3, nd4, nd5, nd6, nd7, 6 * (b + 1));
    } else {
      // tail descriptors (steps 1994..1999) from carry + chunk 499
      int4 t = sp[499];
      MKRD(nd0, cc0, cc1, t.x);
      MKRD(nd1, t.y, t.z, t.w);
      nd2 = nd3 = nd4 = nd5 = nd6 = nd7 = 0;
    }

    PF(T2v, E2v, rd2); ROUND(T0v, E0v);
    PF(T3v, E3v, rd3); ROUND(T1v, E1v);
    PF(T0v, E0v, rd4); ROUND(T2v, E2v);
    PF(T1v, E1v, rd5); ROUND(T3v, E3v);
    PF(T2v, E2v, rd6); ROUND(T0v, E0v);
    PF(T3v, E3v, rd7); ROUND(T1v, E1v);
    PF(T0v, E0v, nd0); ROUND(T2v, E2v);
    PF(T1v, E1v, nd1); ROUND(T3v, E3v);
    RENORM();

    rd0 = nd0; rd1 = nd1; rd2 = nd2; rd3 = nd3;
    rd4 = nd4; rd5 = nd5; rd6 = nd6; rd7 = nd7;
  }

  // --- tail: 2 rounds (T0v/E0v, T1v/E1v already prefetched) ----------------
  ROUND(T0v, E0v);
  ROUND(T1v, E1v);
  RENORM();

  if (lane == 0) out[row] = (__log2f(zlast) + K) * 0.69314718055994530942f;
}

// ---------------------------------------------------------------------------
extern "C" void kernel_launch(void* const* d_in, const int* in_sizes, int n_in,
                              void* d_out, int out_size) {
  const float* w  = (const float*)d_in[0];   // transition_kernel (240)
  const float* ew = (const float*)d_in[1];   // emission_kernel (1088)
  const float* ik = (const float*)d_in[2];   // init_kernel (24)
  const int* seq  = (const int*)d_in[3];     // (batch, T)
  float* out = (float*)d_out;

  int batch = out_size;                      // 2048
  int T = in_sizes[3] / batch;               // 2000

  setup1_kernel<<<1, 512>>>(w, ew, ik);
  setup2_kernel<<<1296, 32>>>();
  fwd_kernel<<<batch / 4, 128>>>(seq, out, T);
}